// round 11
// baseline (speedup 1.0000x reference)
#include <cuda_runtime.h>
#include <cstdint>

#define BB 2
#define LL 2048
#define HH 16
#define EE 64
#define NKT 32

// Frag-major packed operands (tf32 bits). One warp LDG.128 = 32 consecutive uint4.
//  g_Qf/g_Kf: [bh][rowgrp(256)][kbp(4)][lane(32)]
//  g_Vf:      [bh][kt(32)][nbp(4)][db(8)][lane(32)]
__device__ uint4 g_Qf[BB * HH * 256 * 4 * 32];
__device__ uint4 g_Kf[BB * HH * 256 * 4 * 32];
__device__ uint4 g_Vf[BB * HH * NKT * 4 * 8 * 32];

#define LOG2E 1.4426950408889634f
#define SCL2  0.18033688011112042592f   // 0.125 * log2(e)

__device__ __forceinline__ uint32_t f2tf(float x) {
    uint32_t u;
    asm("cvt.rna.tf32.f32 %0, %1;" : "=r"(u) : "f"(x));
    return u;
}
__device__ __forceinline__ float ex2f(float x) {
    float o;
    asm("ex2.approx.f32 %0, %1;" : "=f"(o) : "f"(x));
    return o;
}
__device__ __forceinline__ void mma8(float c[4], uint32_t a0, uint32_t a1,
                                     uint32_t a2, uint32_t a3,
                                     uint32_t b0, uint32_t b1) {
    asm volatile(
        "mma.sync.aligned.m16n8k8.row.col.f32.tf32.tf32.f32 "
        "{%0,%1,%2,%3}, {%4,%5,%6,%7}, {%8,%9}, {%0,%1,%2,%3};"
        : "+f"(c[0]), "+f"(c[1]), "+f"(c[2]), "+f"(c[3])
        : "r"(a0), "r"(a1), "r"(a2), "r"(a3), "r"(b0), "r"(b1));
}

// ---------------------------------------------------------------------------
// Fused prepass: per (kt, h, b) 64-row tile — RoPE Q/K inline, then
// frag-major pack of Q, K, V.  (Unchanged from R10 — proven.)
// ---------------------------------------------------------------------------
__global__ void prep_kernel(const float* __restrict__ q,
                            const float* __restrict__ k,
                            const float* __restrict__ v) {
    __shared__ float sq[64 * 65];
    __shared__ float sk[64 * 65];
    const int kt = blockIdx.x, h = blockIdx.y, b = blockIdx.z;
    const int bh = b * HH + h;
    const int tid = threadIdx.x;

    #pragma unroll
    for (int it = 0; it < 4; it++) {
        int i = it * 256 + tid;
        int j = i >> 4, e4 = i & 15;
        int l = kt * 64 + j;
        size_t gidx = ((size_t)(b * LL + l) * HH + h) * 16 + e4;
        float4 vq = ((const float4*)q)[gidx];
        float4 vk = ((const float4*)k)[gidx];
        if (e4 < 8) {
            float i0 = (float)(e4 * 2);
            const float NEG_L2 = -0.83048202372184058696f;  // -log2(10000)/16
            float s0, c0, s1, c1;
            sincosf((float)l * exp2f(i0 * NEG_L2), &s0, &c0);
            sincosf((float)l * exp2f((i0 + 1.0f) * NEG_L2), &s1, &c1);
            float4 o;
            o.x = c0 * vq.x - s0 * vq.y;  o.y = c0 * vq.y + s0 * vq.x;
            o.z = c1 * vq.z - s1 * vq.w;  o.w = c1 * vq.w + s1 * vq.z;
            vq = o;
            o.x = c0 * vk.x - s0 * vk.y;  o.y = c0 * vk.y + s0 * vk.x;
            o.z = c1 * vk.z - s1 * vk.w;  o.w = c1 * vk.w + s1 * vk.z;
            vk = o;
        }
        int e = e4 * 4;
        sq[j * 65 + e + 0] = vq.x; sq[j * 65 + e + 1] = vq.y;
        sq[j * 65 + e + 2] = vq.z; sq[j * 65 + e + 3] = vq.w;
        sk[j * 65 + e + 0] = vk.x; sk[j * 65 + e + 1] = vk.y;
        sk[j * 65 + e + 2] = vk.z; sk[j * 65 + e + 3] = vk.w;
    }
    __syncthreads();

    uint4* Qf = g_Qf + ((size_t)bh * 256 + kt * 8) * 128;
    uint4* Kf = g_Kf + ((size_t)bh * 256 + kt * 8) * 128;
    #pragma unroll
    for (int it = 0; it < 4; it++) {
        int i = it * 256 + tid;
        int lane = i & 31, x = i >> 5;       // x = nb*4 + kbp
        int nb = x >> 2, kbp = x & 3;
        int g = lane >> 2, t = lane & 3;
        const float* qs = sq + (nb * 8 + g) * 65 + kbp * 16 + t;
        uint4 o;
        o.x = f2tf(qs[0]); o.y = f2tf(qs[4]); o.z = f2tf(qs[8]); o.w = f2tf(qs[12]);
        Qf[x * 32 + lane] = o;
        const float* ks = sk + (nb * 8 + g) * 65 + kbp * 16 + t;
        o.x = f2tf(ks[0]); o.y = f2tf(ks[4]); o.z = f2tf(ks[8]); o.w = f2tf(ks[12]);
        Kf[x * 32 + lane] = o;
    }
    __syncthreads();

    const float* Vg = v + ((size_t)(b * LL + kt * 64) * HH + h) * EE;
    #pragma unroll
    for (int it = 0; it < 4; it++) {
        int i = it * 256 + tid;
        int j = i >> 4, e = (i & 15) * 4;
        float4 w = *(const float4*)(Vg + (size_t)j * (HH * EE) + e);
        sq[j * 65 + e + 0] = w.x; sq[j * 65 + e + 1] = w.y;
        sq[j * 65 + e + 2] = w.z; sq[j * 65 + e + 3] = w.w;
    }
    __syncthreads();

    uint4* Vf = g_Vf + ((size_t)bh * NKT + kt) * 1024;
    #pragma unroll
    for (int it = 0; it < 4; it++) {
        int i = it * 256 + tid;
        int lane = i & 31, x = i >> 5;       // x = nbp*8 + db
        int nbp = x >> 3, db = x & 7;
        int g = lane >> 2, t = lane & 3;
        const float* vb = sq + (16 * nbp + t) * 65 + db * 8 + g;
        uint4 o;
        o.x = f2tf(vb[0]);
        o.y = f2tf(vb[4 * 65]);
        o.z = f2tf(vb[8 * 65]);
        o.w = f2tf(vb[12 * 65]);
        Vf[x * 32 + lane] = o;
    }
}

// ---------------------------------------------------------------------------
// Main attention: R10 structure with lazy Q/K frag loads (all L1 hits) to
// fit the 85-reg / 3-CTA budget -> 24 warps/SM.
// 256 threads = 8 warps; CTA = 128 query rows (vars A: 0-63, B: 64-127).
// Warp w owns the depth-w paired tile; mask threshold 8w+g -> exactly w+1
// key blocks (exact triangle). Static unroll, warp-uniform prunes.
// ---------------------------------------------------------------------------
__global__ __launch_bounds__(256, 3)
void attn8(const float* __restrict__ bw, float* __restrict__ out) {
    const int tid  = threadIdx.x;
    const int lane = tid & 31;
    const int w    = tid >> 5;       // warp = tile depth 0..7
    const int g    = lane >> 2;
    const int t    = lane & 3;
    const int qtb  = blockIdx.x;
    const int h    = blockIdx.y;
    const int b    = blockIdx.z;
    const int bh   = b * HH + h;
    const int l0   = qtb * 128;

    const float b2s = bw[HH + h] * LOG2E;
    const float b2d = bw[h] * LOG2E;

    const int rA = 8 * w + g;        // var-A local row; var-B row = rA + 64
    const int n0 = rA;               // mask threshold (both halves)

    // Q frag base (var-A rowgrp; var-B at +8*128). Loaded lazily per kbp.
    const uint4* Qfb = g_Qf + ((size_t)bh * 256 + qtb * 16 + w) * 128 + lane;

    float oacc[8][4];
    #pragma unroll
    for (int db = 0; db < 8; db++)
        #pragma unroll
        for (int i = 0; i < 4; i++) oacc[db][i] = 0.0f;
    float lsA = 0.0f, lsB = 0.0f;

    const int  src0 = (lane & ~3) + (t >> 1);
    const int  src1 = src0 + 2;
    const bool odd  = (t & 1);

    const uint4* Kf0 = g_Kf + (size_t)bh * 256 * 128 + lane;
    const uint4* Vf0 = g_Vf + (size_t)bh * NKT * 1024 + lane;

    for (int kt = 0; kt < NKT; kt++) {
        const uint4* Kt = Kf0 + (size_t)kt * 8 * 128;
        const uint4* Vt = Vf0 + (size_t)kt * 1024;
        const float biasA = (kt == 2 * qtb)     ? b2s : b2d;
        const float biasB = (kt == 2 * qtb + 1) ? b2s : b2d;

        #pragma unroll
        for (int nbp = 0; nbp < 4; nbp++) {
            const int nb0 = 2 * nbp, nb1 = nb0 + 1;
            if (nb0 > w) continue;              // warp-uniform prune
            const bool a1 = (nb1 <= w);

            // ---- S = Q K^T, lazy Q/K frag loads per kbp (L1 hits) ----
            float c0[4] = {0, 0, 0, 0}, c1[4] = {0, 0, 0, 0};
            #pragma unroll
            for (int kbp = 0; kbp < 4; kbp++) {
                uint4 qx = Qfb[kbp * 32];             // var-A rowgrp
                uint4 qy = Qfb[8 * 128 + kbp * 32];   // var-B rowgrp
                uint4 k0 = Kt[nb0 * 128 + kbp * 32];
                mma8(c0, qx.x, qy.x, qx.y, qy.y, k0.x, k0.y);
                mma8(c0, qx.z, qy.z, qx.w, qy.w, k0.z, k0.w);
                if (a1) {
                    uint4 k1 = Kt[nb1 * 128 + kbp * 32];
                    mma8(c1, qx.x, qy.x, qx.y, qy.y, k1.x, k1.y);
                    mma8(c1, qx.z, qy.z, qx.w, qy.w, k1.z, k1.w);
                }
            }

            // ---- softmax + P frag relayout (quad shuffles) ----
            uint32_t pa0[4], pa1[4];
            #pragma unroll
            for (int nbi = 0; nbi < 2; nbi++) {
                if (nbi && !a1) continue;
                float* c = nbi ? c1 : c0;
                const int ci = (nb0 + nbi) * 8 + 2 * t;
                float p0 = (ci     <= n0) ? ex2f(fmaf(c[0], SCL2, biasA)) : 0.0f;
                float p1 = (ci + 1 <= n0) ? ex2f(fmaf(c[1], SCL2, biasA)) : 0.0f;
                float p2 = (ci     <= n0) ? ex2f(fmaf(c[2], SCL2, biasB)) : 0.0f;
                float p3 = (ci + 1 <= n0) ? ex2f(fmaf(c[3], SCL2, biasB)) : 0.0f;
                lsA += p0 + p1;
                lsB += p2 + p3;
                uint32_t* pa = nbi ? pa1 : pa0;
                uint32_t u0 = f2tf(p0), u1 = f2tf(p1), u2 = f2tf(p2), u3 = f2tf(p3);
                uint32_t x0 = __shfl_sync(0xffffffffu, u0, src0);
                uint32_t x1 = __shfl_sync(0xffffffffu, u1, src0);
                pa[0] = odd ? x1 : x0;
                uint32_t y0 = __shfl_sync(0xffffffffu, u2, src0);
                uint32_t y1 = __shfl_sync(0xffffffffu, u3, src0);
                pa[1] = odd ? y1 : y0;
                uint32_t z0 = __shfl_sync(0xffffffffu, u0, src1);
                uint32_t z1 = __shfl_sync(0xffffffffu, u1, src1);
                pa[2] = odd ? z1 : z0;
                uint32_t w0 = __shfl_sync(0xffffffffu, u2, src1);
                uint32_t w1 = __shfl_sync(0xffffffffu, u3, src1);
                pa[3] = odd ? w1 : w0;
            }

            // ---- O += P V (coalesced V frag loads; x,y = nb0, z,w = nb1) ----
            #pragma unroll
            for (int db = 0; db < 8; db++) {
                uint4 vq = Vt[nbp * 256 + db * 32];
                mma8(oacc[db], pa0[0], pa0[1], pa0[2], pa0[3], vq.x, vq.y);
                if (a1) mma8(oacc[db], pa1[0], pa1[1], pa1[2], pa1[3], vq.z, vq.w);
            }
        }
    }

    // ---- reduce row sums across quad, normalize, store ----
    lsA += __shfl_xor_sync(0xffffffffu, lsA, 1);
    lsA += __shfl_xor_sync(0xffffffffu, lsA, 2);
    lsB += __shfl_xor_sync(0xffffffffu, lsB, 1);
    lsB += __shfl_xor_sync(0xffffffffu, lsB, 2);
    const float invA = 1.0f / lsA;
    const float invB = 1.0f / lsB;

    const int rowA = l0 + rA;
    const int rowB = rowA + 64;
    #pragma unroll
    for (int db = 0; db < 8; db++) {
        float2 v0;
        v0.x = oacc[db][0] * invA;
        v0.y = oacc[db][1] * invA;
        *(float2*)(out + (((size_t)(b * LL + rowA)) * HH + h) * EE + db * 8 + 2 * t) = v0;
        float2 v1;
        v1.x = oacc[db][2] * invB;
        v1.y = oacc[db][3] * invB;
        *(float2*)(out + (((size_t)(b * LL + rowB)) * HH + h) * EE + db * 8 + 2 * t) = v1;
    }
}

// ---------------------------------------------------------------------------
extern "C" void kernel_launch(void* const* d_in, const int* in_sizes, int n_in,
                              void* d_out, int out_size) {
    const float* q  = (const float*)d_in[0];
    const float* k  = (const float*)d_in[1];
    const float* v  = (const float*)d_in[2];
    const float* bw = (const float*)d_in[3];
    float* out = (float*)d_out;

    prep_kernel<<<dim3(NKT, HH, BB), 256>>>(q, k, v);

    dim3 grid(LL / 128, HH, BB);
    attn8<<<grid, 256>>>(bw, out);
}

// round 12
// speedup vs baseline: 3.4590x; 3.4590x over previous
#include <cuda_runtime.h>
#include <cstdint>

#define BB 2
#define LL 2048
#define HH 16
#define EE 64
#define NKT 32

// fp16x2 frag-major packed operands. One warp LDG.128 = 32 consecutive uint4.
//  g_Qh/g_Kh: [bh][grp(256)][kbp2(2)][lane(32)]
//    grp = 8-row group; per lane(g,t), kbp2 covers dims [32*kbp2, 32*kbp2+32):
//    .x = (row g dims 2t,2t+1)+0   .y = +8   .z = +16   .w = +24   (fp16x2 each)
//  g_Vh: [bh][kt(32)][nbp(4)][db2(4)][lane(32)]
//    .x = (keys 16nbp+2t,+1 @ col 16db2+g)  .y = keys +8  .z/.w = col +8
__device__ uint4 g_Qh[BB * HH * 256 * 2 * 32];
__device__ uint4 g_Kh[BB * HH * 256 * 2 * 32];
__device__ uint4 g_Vh[BB * HH * NKT * 16 * 32];

#define LOG2E 1.4426950408889634f
#define SCL2  0.18033688011112042592f   // 0.125 * log2(e)

__device__ __forceinline__ uint32_t packh2(float lo, float hi) {
    uint32_t r;   // cvt.f16x2: first source -> high half
    asm("cvt.rn.f16x2.f32 %0, %1, %2;" : "=r"(r) : "f"(hi), "f"(lo));
    return r;
}
__device__ __forceinline__ float ex2f(float x) {
    float o;
    asm("ex2.approx.f32 %0, %1;" : "=f"(o) : "f"(x));
    return o;
}
__device__ __forceinline__ void mma16(float c[4], uint32_t a0, uint32_t a1,
                                      uint32_t a2, uint32_t a3,
                                      uint32_t b0, uint32_t b1) {
    asm volatile(
        "mma.sync.aligned.m16n8k16.row.col.f32.f16.f16.f32 "
        "{%0,%1,%2,%3}, {%4,%5,%6,%7}, {%8,%9}, {%0,%1,%2,%3};"
        : "+f"(c[0]), "+f"(c[1]), "+f"(c[2]), "+f"(c[3])
        : "r"(a0), "r"(a1), "r"(a2), "r"(a3), "r"(b0), "r"(b1));
}

// ---------------------------------------------------------------------------
// Fused prepass per (kt, h, b) 64-row tile: RoPE Q/K inline, then fp16
// frag-major pack of Q, K, V.
// ---------------------------------------------------------------------------
__global__ void prep_kernel(const float* __restrict__ q,
                            const float* __restrict__ k,
                            const float* __restrict__ v) {
    __shared__ float sq[64 * 65];
    __shared__ float sk[64 * 65];
    const int kt = blockIdx.x, h = blockIdx.y, b = blockIdx.z;
    const int bh = b * HH + h;
    const int tid = threadIdx.x;

    // ---- load Q,K rows, RoPE, into smem ----
    #pragma unroll
    for (int it = 0; it < 4; it++) {
        int i = it * 256 + tid;
        int j = i >> 4, e4 = i & 15;
        int l = kt * 64 + j;
        size_t gidx = ((size_t)(b * LL + l) * HH + h) * 16 + e4;
        float4 vq = ((const float4*)q)[gidx];
        float4 vk = ((const float4*)k)[gidx];
        if (e4 < 8) {
            float i0 = (float)(e4 * 2);
            const float NEG_L2 = -0.83048202372184058696f;  // -log2(10000)/16
            float s0, c0, s1, c1;
            sincosf((float)l * exp2f(i0 * NEG_L2), &s0, &c0);
            sincosf((float)l * exp2f((i0 + 1.0f) * NEG_L2), &s1, &c1);
            float4 o;
            o.x = c0 * vq.x - s0 * vq.y;  o.y = c0 * vq.y + s0 * vq.x;
            o.z = c1 * vq.z - s1 * vq.w;  o.w = c1 * vq.w + s1 * vq.z;
            vq = o;
            o.x = c0 * vk.x - s0 * vk.y;  o.y = c0 * vk.y + s0 * vk.x;
            o.z = c1 * vk.z - s1 * vk.w;  o.w = c1 * vk.w + s1 * vk.z;
            vk = o;
        }
        int e = e4 * 4;
        sq[j * 65 + e + 0] = vq.x; sq[j * 65 + e + 1] = vq.y;
        sq[j * 65 + e + 2] = vq.z; sq[j * 65 + e + 3] = vq.w;
        sk[j * 65 + e + 0] = vk.x; sk[j * 65 + e + 1] = vk.y;
        sk[j * 65 + e + 2] = vk.z; sk[j * 65 + e + 3] = vk.w;
    }
    __syncthreads();

    // ---- pack Q/K: 512 uint4 each (8 grp x 2 kbp2 x 32 lanes) ----
    uint4* Qh = g_Qh + ((size_t)bh * 256 + kt * 8) * 2 * 32;
    uint4* Kh = g_Kh + ((size_t)bh * 256 + kt * 8) * 2 * 32;
    #pragma unroll
    for (int it = 0; it < 2; it++) {
        int i = it * 256 + tid;
        int lane = i & 31, x = i >> 5;       // x = grp*2 + kbp2
        int grp = x >> 1, kbp2 = x & 1;
        int g = lane >> 2, t = lane & 3;
        const float* s = sq + (grp * 8 + g) * 65 + kbp2 * 32 + 2 * t;
        uint4 o;
        o.x = packh2(s[0],  s[1]);
        o.y = packh2(s[8],  s[9]);
        o.z = packh2(s[16], s[17]);
        o.w = packh2(s[24], s[25]);
        Qh[x * 32 + lane] = o;
        const float* s2 = sk + (grp * 8 + g) * 65 + kbp2 * 32 + 2 * t;
        o.x = packh2(s2[0],  s2[1]);
        o.y = packh2(s2[8],  s2[9]);
        o.z = packh2(s2[16], s2[17]);
        o.w = packh2(s2[24], s2[25]);
        Kh[x * 32 + lane] = o;
    }
    __syncthreads();

    // ---- load V tile into sq (reuse), then pack ----
    const float* Vg = v + ((size_t)(b * LL + kt * 64) * HH + h) * EE;
    #pragma unroll
    for (int it = 0; it < 4; it++) {
        int i = it * 256 + tid;
        int j = i >> 4, e = (i & 15) * 4;
        float4 w = *(const float4*)(Vg + (size_t)j * (HH * EE) + e);
        sq[j * 65 + e + 0] = w.x; sq[j * 65 + e + 1] = w.y;
        sq[j * 65 + e + 2] = w.z; sq[j * 65 + e + 3] = w.w;
    }
    __syncthreads();

    // ---- V pack: 512 uint4 (4 nbp x 4 db2 x 32 lanes) ----
    uint4* Vh = g_Vh + ((size_t)bh * NKT + kt) * 16 * 32;
    #pragma unroll
    for (int it = 0; it < 2; it++) {
        int i = it * 256 + tid;
        int lane = i & 31, x = i >> 5;       // x = nbp*4 + db2
        int nbp = x >> 2, db2 = x & 3;
        int g = lane >> 2, t = lane & 3;
        const float* v0 = sq + (16 * nbp + 2 * t) * 65 + 16 * db2 + g;
        uint4 o;
        o.x = packh2(v0[0],        v0[65]);          // keys +0,+1   col even-db
        o.y = packh2(v0[8 * 65],   v0[9 * 65]);      // keys +8,+9
        o.z = packh2(v0[8],        v0[65 + 8]);      // col odd-db (+8)
        o.w = packh2(v0[8 * 65 + 8], v0[9 * 65 + 8]);
        Vh[x * 32 + lane] = o;
    }
}

// ---------------------------------------------------------------------------
// Main attention, fp16 m16n8k16. 256 threads = 8 warps; CTA = 128 query
// rows (vars A: 0-63, B: 64-127). Warp w owns the depth-w paired tile
// (A-frag rows 0-7 = var-A group w, rows 8-15 = var-B group w); mask
// threshold 8w+g -> exactly w+1 key blocks. C-frag -> A-frag is an
// identity on thread ownership for fp16, so P needs NO shuffles.
// ---------------------------------------------------------------------------
__global__ __launch_bounds__(256, 3)
void attn9(const float* __restrict__ bw, float* __restrict__ out) {
    const int tid  = threadIdx.x;
    const int lane = tid & 31;
    const int w    = tid >> 5;       // warp = tile depth 0..7
    const int g    = lane >> 2;
    const int t    = lane & 3;
    const int qtb  = blockIdx.x;
    const int h    = blockIdx.y;
    const int b    = blockIdx.z;
    const int bh   = b * HH + h;
    const int l0   = qtb * 128;

    const float b2s = bw[HH + h] * LOG2E;
    const float b2d = bw[h] * LOG2E;

    const int rA = 8 * w + g;        // var-A local row; var-B row = rA + 64
    const int n0 = rA;               // mask threshold (both halves)

    // ---- persistent Q A-frags: 4 coalesced LDG.128 -> 16 regs ----
    const uint4* QhA = g_Qh + ((size_t)bh * 256 + qtb * 16 + w) * 64 + lane;
    const uint4* QhB = QhA + 8 * 64;     // var-B group (+8 grps)
    uint32_t qa[4][4];
    {
        uint4 a0 = QhA[0],  a1 = QhA[32];
        uint4 b0 = QhB[0],  b1 = QhB[32];
        qa[0][0] = a0.x; qa[0][1] = b0.x; qa[0][2] = a0.y; qa[0][3] = b0.y;
        qa[1][0] = a0.z; qa[1][1] = b0.z; qa[1][2] = a0.w; qa[1][3] = b0.w;
        qa[2][0] = a1.x; qa[2][1] = b1.x; qa[2][2] = a1.y; qa[2][3] = b1.y;
        qa[3][0] = a1.z; qa[3][1] = b1.z; qa[3][2] = a1.w; qa[3][3] = b1.w;
    }

    float oacc[8][4];
    #pragma unroll
    for (int db = 0; db < 8; db++)
        #pragma unroll
        for (int i = 0; i < 4; i++) oacc[db][i] = 0.0f;
    float lsA = 0.0f, lsB = 0.0f;

    const uint4* Kf0 = g_Kh + (size_t)bh * 256 * 64 + lane;
    const uint4* Vf0 = g_Vh + (size_t)bh * NKT * 512 + lane;

    for (int kt = 0; kt < NKT; kt++) {
        const uint4* Kt = Kf0 + (size_t)kt * 8 * 64;
        const uint4* Vt = Vf0 + (size_t)kt * 512;
        const float biasA = (kt == 2 * qtb)     ? b2s : b2d;
        const float biasB = (kt == 2 * qtb + 1) ? b2s : b2d;

        #pragma unroll
        for (int nbp = 0; nbp < 4; nbp++) {
            const int nb0 = 2 * nbp, nb1 = nb0 + 1;
            if (nb0 > w) continue;              // warp-uniform prune
            const bool a1 = (nb1 <= w);

            // ---- S = Q K^T (4-deep chains; K via 2 LDG.128 per nb) ----
            float c0[4] = {0, 0, 0, 0}, c1[4] = {0, 0, 0, 0};
            {
                uint4 k0 = Kt[nb0 * 64], k1 = Kt[nb0 * 64 + 32];
                mma16(c0, qa[0][0], qa[0][1], qa[0][2], qa[0][3], k0.x, k0.y);
                mma16(c0, qa[1][0], qa[1][1], qa[1][2], qa[1][3], k0.z, k0.w);
                mma16(c0, qa[2][0], qa[2][1], qa[2][2], qa[2][3], k1.x, k1.y);
                mma16(c0, qa[3][0], qa[3][1], qa[3][2], qa[3][3], k1.z, k1.w);
            }
            if (a1) {
                uint4 k0 = Kt[nb1 * 64], k1 = Kt[nb1 * 64 + 32];
                mma16(c1, qa[0][0], qa[0][1], qa[0][2], qa[0][3], k0.x, k0.y);
                mma16(c1, qa[1][0], qa[1][1], qa[1][2], qa[1][3], k0.z, k0.w);
                mma16(c1, qa[2][0], qa[2][1], qa[2][2], qa[2][3], k1.x, k1.y);
                mma16(c1, qa[3][0], qa[3][1], qa[3][2], qa[3][3], k1.z, k1.w);
            }

            // ---- softmax; P C-frag -> A-frag is shuffle-free for fp16 ----
            uint32_t pa0, pa1, pa2, pa3;
            {
                const int ci = nb0 * 8 + 2 * t;
                float p0 = (ci     <= n0) ? ex2f(fmaf(c0[0], SCL2, biasA)) : 0.0f;
                float p1 = (ci + 1 <= n0) ? ex2f(fmaf(c0[1], SCL2, biasA)) : 0.0f;
                float p2 = (ci     <= n0) ? ex2f(fmaf(c0[2], SCL2, biasB)) : 0.0f;
                float p3 = (ci + 1 <= n0) ? ex2f(fmaf(c0[3], SCL2, biasB)) : 0.0f;
                lsA += p0 + p1;
                lsB += p2 + p3;
                pa0 = packh2(p0, p1);   // row g    (var A), cols 2t,2t+1
                pa1 = packh2(p2, p3);   // row g+8  (var B)
            }
            if (a1) {
                const int ci = nb1 * 8 + 2 * t;
                float p0 = (ci     <= n0) ? ex2f(fmaf(c1[0], SCL2, biasA)) : 0.0f;
                float p1 = (ci + 1 <= n0) ? ex2f(fmaf(c1[1], SCL2, biasA)) : 0.0f;
                float p2 = (ci     <= n0) ? ex2f(fmaf(c1[2], SCL2, biasB)) : 0.0f;
                float p3 = (ci + 1 <= n0) ? ex2f(fmaf(c1[3], SCL2, biasB)) : 0.0f;
                lsA += p0 + p1;
                lsB += p2 + p3;
                pa2 = packh2(p0, p1);   // k-cols 8+2t (nb1 half)
                pa3 = packh2(p2, p3);
            } else {
                pa2 = 0u; pa3 = 0u;
            }

            // ---- O += P V (one k16 mma per db; 4 LDG.128 per nbp) ----
            #pragma unroll
            for (int db2 = 0; db2 < 4; db2++) {
                uint4 vv = Vt[(nbp * 4 + db2) * 32];
                mma16(oacc[2 * db2],     pa0, pa1, pa2, pa3, vv.x, vv.y);
                mma16(oacc[2 * db2 + 1], pa0, pa1, pa2, pa3, vv.z, vv.w);
            }
        }
    }

    // ---- reduce row sums across quad, normalize, store ----
    lsA += __shfl_xor_sync(0xffffffffu, lsA, 1);
    lsA += __shfl_xor_sync(0xffffffffu, lsA, 2);
    lsB += __shfl_xor_sync(0xffffffffu, lsB, 1);
    lsB += __shfl_xor_sync(0xffffffffu, lsB, 2);
    const float invA = 1.0f / lsA;
    const float invB = 1.0f / lsB;

    const int rowA = l0 + rA;
    const int rowB = rowA + 64;
    #pragma unroll
    for (int db = 0; db < 8; db++) {
        float2 v0;
        v0.x = oacc[db][0] * invA;
        v0.y = oacc[db][1] * invA;
        *(float2*)(out + (((size_t)(b * LL + rowA)) * HH + h) * EE + db * 8 + 2 * t) = v0;
        float2 v1;
        v1.x = oacc[db][2] * invB;
        v1.y = oacc[db][3] * invB;
        *(float2*)(out + (((size_t)(b * LL + rowB)) * HH + h) * EE + db * 8 + 2 * t) = v1;
    }
}

// ---------------------------------------------------------------------------
extern "C" void kernel_launch(void* const* d_in, const int* in_sizes, int n_in,
                              void* d_out, int out_size) {
    const float* q  = (const float*)d_in[0];
    const float* k  = (const float*)d_in[1];
    const float* v  = (const float*)d_in[2];
    const float* bw = (const float*)d_in[3];
    float* out = (float*)d_out;

    prep_kernel<<<dim3(NKT, HH, BB), 256>>>(q, k, v);

    dim3 grid(LL / 128, HH, BB);
    attn9<<<grid, 256>>>(bw, out);
}

// round 13
// speedup vs baseline: 4.6592x; 1.3470x over previous
#include <cuda_runtime.h>
#include <cstdint>

#define BB 2
#define LL 2048
#define HH 16
#define EE 64
#define NKT 32

// fp16x2 frag-major packed operands. One warp LDG.128 = 32 consecutive uint4.
//  g_Qh/g_Kh: [bh][grp(256)][kbp2(2)][lane(32)]
//    grp = 8-row group; per lane(g,t), kbp2 covers dims [32*kbp2, 32*kbp2+32):
//    .x = (row g dims 2t,2t+1)+0   .y = +8   .z = +16   .w = +24   (fp16x2 each)
//  g_Vh: [bh][kt(32)][nbp(4)][db2(4)][lane(32)]
__device__ uint4 g_Qh[BB * HH * 256 * 2 * 32];
__device__ uint4 g_Kh[BB * HH * 256 * 2 * 32];
__device__ uint4 g_Vh[BB * HH * NKT * 16 * 32];

#define LOG2E 1.4426950408889634f
#define SCL2  0.18033688011112042592f   // 0.125 * log2(e)

__device__ __forceinline__ uint32_t packh2(float lo, float hi) {
    uint32_t r;
    asm("cvt.rn.f16x2.f32 %0, %1, %2;" : "=r"(r) : "f"(hi), "f"(lo));
    return r;
}
__device__ __forceinline__ float ex2f(float x) {
    float o;
    asm("ex2.approx.f32 %0, %1;" : "=f"(o) : "f"(x));
    return o;
}
__device__ __forceinline__ void mma16(float c[4], uint32_t a0, uint32_t a1,
                                      uint32_t a2, uint32_t a3,
                                      uint32_t b0, uint32_t b1) {
    asm volatile(
        "mma.sync.aligned.m16n8k16.row.col.f32.f16.f16.f32 "
        "{%0,%1,%2,%3}, {%4,%5,%6,%7}, {%8,%9}, {%0,%1,%2,%3};"
        : "+f"(c[0]), "+f"(c[1]), "+f"(c[2]), "+f"(c[3])
        : "r"(a0), "r"(a1), "r"(a2), "r"(a3), "r"(b0), "r"(b1));
}

// ---------------------------------------------------------------------------
// Fused prepass (unchanged from R12 — proven).
// ---------------------------------------------------------------------------
__global__ void prep_kernel(const float* __restrict__ q,
                            const float* __restrict__ k,
                            const float* __restrict__ v) {
    __shared__ float sq[64 * 65];
    __shared__ float sk[64 * 65];
    const int kt = blockIdx.x, h = blockIdx.y, b = blockIdx.z;
    const int bh = b * HH + h;
    const int tid = threadIdx.x;

    #pragma unroll
    for (int it = 0; it < 4; it++) {
        int i = it * 256 + tid;
        int j = i >> 4, e4 = i & 15;
        int l = kt * 64 + j;
        size_t gidx = ((size_t)(b * LL + l) * HH + h) * 16 + e4;
        float4 vq = ((const float4*)q)[gidx];
        float4 vk = ((const float4*)k)[gidx];
        if (e4 < 8) {
            float i0 = (float)(e4 * 2);
            const float NEG_L2 = -0.83048202372184058696f;  // -log2(10000)/16
            float s0, c0, s1, c1;
            sincosf((float)l * exp2f(i0 * NEG_L2), &s0, &c0);
            sincosf((float)l * exp2f((i0 + 1.0f) * NEG_L2), &s1, &c1);
            float4 o;
            o.x = c0 * vq.x - s0 * vq.y;  o.y = c0 * vq.y + s0 * vq.x;
            o.z = c1 * vq.z - s1 * vq.w;  o.w = c1 * vq.w + s1 * vq.z;
            vq = o;
            o.x = c0 * vk.x - s0 * vk.y;  o.y = c0 * vk.y + s0 * vk.x;
            o.z = c1 * vk.z - s1 * vk.w;  o.w = c1 * vk.w + s1 * vk.z;
            vk = o;
        }
        int e = e4 * 4;
        sq[j * 65 + e + 0] = vq.x; sq[j * 65 + e + 1] = vq.y;
        sq[j * 65 + e + 2] = vq.z; sq[j * 65 + e + 3] = vq.w;
        sk[j * 65 + e + 0] = vk.x; sk[j * 65 + e + 1] = vk.y;
        sk[j * 65 + e + 2] = vk.z; sk[j * 65 + e + 3] = vk.w;
    }
    __syncthreads();

    uint4* Qh = g_Qh + ((size_t)bh * 256 + kt * 8) * 2 * 32;
    uint4* Kh = g_Kh + ((size_t)bh * 256 + kt * 8) * 2 * 32;
    #pragma unroll
    for (int it = 0; it < 2; it++) {
        int i = it * 256 + tid;
        int lane = i & 31, x = i >> 5;       // x = grp*2 + kbp2
        int grp = x >> 1, kbp2 = x & 1;
        int g = lane >> 2, t = lane & 3;
        const float* s = sq + (grp * 8 + g) * 65 + kbp2 * 32 + 2 * t;
        uint4 o;
        o.x = packh2(s[0],  s[1]);
        o.y = packh2(s[8],  s[9]);
        o.z = packh2(s[16], s[17]);
        o.w = packh2(s[24], s[25]);
        Qh[x * 32 + lane] = o;
        const float* s2 = sk + (grp * 8 + g) * 65 + kbp2 * 32 + 2 * t;
        o.x = packh2(s2[0],  s2[1]);
        o.y = packh2(s2[8],  s2[9]);
        o.z = packh2(s2[16], s2[17]);
        o.w = packh2(s2[24], s2[25]);
        Kh[x * 32 + lane] = o;
    }
    __syncthreads();

    const float* Vg = v + ((size_t)(b * LL + kt * 64) * HH + h) * EE;
    #pragma unroll
    for (int it = 0; it < 4; it++) {
        int i = it * 256 + tid;
        int j = i >> 4, e = (i & 15) * 4;
        float4 w = *(const float4*)(Vg + (size_t)j * (HH * EE) + e);
        sq[j * 65 + e + 0] = w.x; sq[j * 65 + e + 1] = w.y;
        sq[j * 65 + e + 2] = w.z; sq[j * 65 + e + 3] = w.w;
    }
    __syncthreads();

    uint4* Vh = g_Vh + ((size_t)bh * NKT + kt) * 16 * 32;
    #pragma unroll
    for (int it = 0; it < 2; it++) {
        int i = it * 256 + tid;
        int lane = i & 31, x = i >> 5;       // x = nbp*4 + db2
        int nbp = x >> 2, db2 = x & 3;
        int g = lane >> 2, t = lane & 3;
        const float* v0 = sq + (16 * nbp + 2 * t) * 65 + 16 * db2 + g;
        uint4 o;
        o.x = packh2(v0[0],        v0[65]);
        o.y = packh2(v0[8 * 65],   v0[9 * 65]);
        o.z = packh2(v0[8],        v0[65 + 8]);
        o.w = packh2(v0[8 * 65 + 8], v0[9 * 65 + 8]);
        Vh[x * 32 + lane] = o;
    }
}

// ---------------------------------------------------------------------------
// One tile's blocks at one kt. NBPN = static nbp trip count.
// ---------------------------------------------------------------------------
template <int NBPN>
__device__ __forceinline__ void tile_kt(
    int dep, int n0, const uint32_t (&qa)[4][4],
    const uint4* __restrict__ Kt, const uint4* __restrict__ Vt,
    float biasA, float biasB, int t,
    float (&oacc)[8][4], float& lsA, float& lsB)
{
    #pragma unroll
    for (int nbp = 0; nbp < NBPN; nbp++) {
        const int nb0 = 2 * nbp, nb1 = nb0 + 1;
        if (nb0 > dep) continue;              // warp-uniform prune
        const bool a1 = (nb1 <= dep);

        float c0[4] = {0, 0, 0, 0}, c1[4] = {0, 0, 0, 0};
        {
            uint4 k0 = Kt[nb0 * 64], k1 = Kt[nb0 * 64 + 32];
            mma16(c0, qa[0][0], qa[0][1], qa[0][2], qa[0][3], k0.x, k0.y);
            mma16(c0, qa[1][0], qa[1][1], qa[1][2], qa[1][3], k0.z, k0.w);
            mma16(c0, qa[2][0], qa[2][1], qa[2][2], qa[2][3], k1.x, k1.y);
            mma16(c0, qa[3][0], qa[3][1], qa[3][2], qa[3][3], k1.z, k1.w);
        }
        if (a1) {
            uint4 k0 = Kt[nb1 * 64], k1 = Kt[nb1 * 64 + 32];
            mma16(c1, qa[0][0], qa[0][1], qa[0][2], qa[0][3], k0.x, k0.y);
            mma16(c1, qa[1][0], qa[1][1], qa[1][2], qa[1][3], k0.z, k0.w);
            mma16(c1, qa[2][0], qa[2][1], qa[2][2], qa[2][3], k1.x, k1.y);
            mma16(c1, qa[3][0], qa[3][1], qa[3][2], qa[3][3], k1.z, k1.w);
        }

        uint32_t pa0, pa1, pa2, pa3;
        {
            const int ci = nb0 * 8 + 2 * t;
            float p0 = (ci     <= n0) ? ex2f(fmaf(c0[0], SCL2, biasA)) : 0.0f;
            float p1 = (ci + 1 <= n0) ? ex2f(fmaf(c0[1], SCL2, biasA)) : 0.0f;
            float p2 = (ci     <= n0) ? ex2f(fmaf(c0[2], SCL2, biasB)) : 0.0f;
            float p3 = (ci + 1 <= n0) ? ex2f(fmaf(c0[3], SCL2, biasB)) : 0.0f;
            lsA += p0 + p1;
            lsB += p2 + p3;
            pa0 = packh2(p0, p1);
            pa1 = packh2(p2, p3);
        }
        if (a1) {
            const int ci = nb1 * 8 + 2 * t;
            float p0 = (ci     <= n0) ? ex2f(fmaf(c1[0], SCL2, biasA)) : 0.0f;
            float p1 = (ci + 1 <= n0) ? ex2f(fmaf(c1[1], SCL2, biasA)) : 0.0f;
            float p2 = (ci     <= n0) ? ex2f(fmaf(c1[2], SCL2, biasB)) : 0.0f;
            float p3 = (ci + 1 <= n0) ? ex2f(fmaf(c1[3], SCL2, biasB)) : 0.0f;
            lsA += p0 + p1;
            lsB += p2 + p3;
            pa2 = packh2(p0, p1);
            pa3 = packh2(p2, p3);
        } else {
            pa2 = 0u; pa3 = 0u;
        }

        #pragma unroll
        for (int db2 = 0; db2 < 4; db2++) {
            uint4 vv = Vt[(nbp * 4 + db2) * 32];
            mma16(oacc[2 * db2],     pa0, pa1, pa2, pa3, vv.x, vv.y);
            mma16(oacc[2 * db2 + 1], pa0, pa1, pa2, pa3, vv.z, vv.w);
        }
    }
}

// ---------------------------------------------------------------------------
// Main attention, balanced dual-tile warps. 128 threads = 4 warps per CTA;
// CTA = 128 query rows (vars A: 0-63, B: 64-127). Warp w owns depth tiles
// {w, 7-w} -> exactly 9 key blocks/kt for EVERY warp (perfect balance,
// exact triangle, no early-exit warp waste). fp16 m16n8k16, shuffle-free P.
// 512 CTAs at 4/SM = single wave.
// ---------------------------------------------------------------------------
__global__ __launch_bounds__(128, 4)
void attn10(const float* __restrict__ bw, float* __restrict__ out) {
    const int tid  = threadIdx.x;
    const int lane = tid & 31;
    const int w    = tid >> 5;       // 0..3
    const int g    = lane >> 2;
    const int t    = lane & 3;
    const int qtb  = blockIdx.x;
    const int h    = blockIdx.y;
    const int b    = blockIdx.z;
    const int bh   = b * HH + h;
    const int l0   = qtb * 128;

    const float b2s = bw[HH + h] * LOG2E;
    const float b2d = bw[h] * LOG2E;

    const int dep0 = w;              // light tile (nbp < 2)
    const int dep1 = 7 - w;          // heavy tile (nbp < 4)
    const int n00  = 8 * dep0 + g;
    const int n01  = 8 * dep1 + g;

    // ---- persistent Q A-frags for both tiles (fp16: 16 regs each) ----
    uint32_t qa0[4][4], qa1[4][4];
    {
        const uint4* QA = g_Qh + ((size_t)bh * 256 + qtb * 16 + dep0) * 64 + lane;
        const uint4* QB = QA + 8 * 64;
        uint4 a0 = QA[0], a1 = QA[32], b0 = QB[0], b1 = QB[32];
        qa0[0][0] = a0.x; qa0[0][1] = b0.x; qa0[0][2] = a0.y; qa0[0][3] = b0.y;
        qa0[1][0] = a0.z; qa0[1][1] = b0.z; qa0[1][2] = a0.w; qa0[1][3] = b0.w;
        qa0[2][0] = a1.x; qa0[2][1] = b1.x; qa0[2][2] = a1.y; qa0[2][3] = b1.y;
        qa0[3][0] = a1.z; qa0[3][1] = b1.z; qa0[3][2] = a1.w; qa0[3][3] = b1.w;
    }
    {
        const uint4* QA = g_Qh + ((size_t)bh * 256 + qtb * 16 + dep1) * 64 + lane;
        const uint4* QB = QA + 8 * 64;
        uint4 a0 = QA[0], a1 = QA[32], b0 = QB[0], b1 = QB[32];
        qa1[0][0] = a0.x; qa1[0][1] = b0.x; qa1[0][2] = a0.y; qa1[0][3] = b0.y;
        qa1[1][0] = a0.z; qa1[1][1] = b0.z; qa1[1][2] = a0.w; qa1[1][3] = b0.w;
        qa1[2][0] = a1.x; qa1[2][1] = b1.x; qa1[2][2] = a1.y; qa1[2][3] = b1.y;
        qa1[3][0] = a1.z; qa1[3][1] = b1.z; qa1[3][2] = a1.w; qa1[3][3] = b1.w;
    }

    float o0[8][4], o1[8][4];
    #pragma unroll
    for (int db = 0; db < 8; db++)
        #pragma unroll
        for (int i = 0; i < 4; i++) { o0[db][i] = 0.0f; o1[db][i] = 0.0f; }
    float lsA0 = 0.0f, lsB0 = 0.0f, lsA1 = 0.0f, lsB1 = 0.0f;

    const uint4* Kf0 = g_Kh + (size_t)bh * 256 * 64 + lane;
    const uint4* Vf0 = g_Vh + (size_t)bh * NKT * 512 + lane;

    for (int kt = 0; kt < NKT; kt++) {
        const uint4* Kt = Kf0 + (size_t)kt * 8 * 64;
        const uint4* Vt = Vf0 + (size_t)kt * 512;
        const float biasA = (kt == 2 * qtb)     ? b2s : b2d;
        const float biasB = (kt == 2 * qtb + 1) ? b2s : b2d;

        tile_kt<2>(dep0, n00, qa0, Kt, Vt, biasA, biasB, t, o0, lsA0, lsB0);
        tile_kt<4>(dep1, n01, qa1, Kt, Vt, biasA, biasB, t, o1, lsA1, lsB1);
    }

    // ---- reduce row sums across quads, normalize, store both tiles ----
    #pragma unroll
    for (int ti = 0; ti < 2; ti++) {
        float lsA = ti ? lsA1 : lsA0;
        float lsB = ti ? lsB1 : lsB0;
        lsA += __shfl_xor_sync(0xffffffffu, lsA, 1);
        lsA += __shfl_xor_sync(0xffffffffu, lsA, 2);
        lsB += __shfl_xor_sync(0xffffffffu, lsB, 1);
        lsB += __shfl_xor_sync(0xffffffffu, lsB, 2);
        const float invA = 1.0f / lsA;
        const float invB = 1.0f / lsB;
        float (*oacc)[4] = ti ? o1 : o0;
        const int dep = ti ? dep1 : dep0;
        const int rowA = l0 + 8 * dep + g;
        const int rowB = rowA + 64;
        #pragma unroll
        for (int db = 0; db < 8; db++) {
            float2 v0;
            v0.x = oacc[db][0] * invA;
            v0.y = oacc[db][1] * invA;
            *(float2*)(out + (((size_t)(b * LL + rowA)) * HH + h) * EE + db * 8 + 2 * t) = v0;
            float2 v1;
            v1.x = oacc[db][2] * invB;
            v1.y = oacc[db][3] * invB;
            *(float2*)(out + (((size_t)(b * LL + rowB)) * HH + h) * EE + db * 8 + 2 * t) = v1;
        }
    }
}

// ---------------------------------------------------------------------------
extern "C" void kernel_launch(void* const* d_in, const int* in_sizes, int n_in,
                              void* d_out, int out_size) {
    const float* q  = (const float*)d_in[0];
    const float* k  = (const float*)d_in[1];
    const float* v  = (const float*)d_in[2];
    const float* bw = (const float*)d_in[3];
    float* out = (float*)d_out;

    prep_kernel<<<dim3(NKT, HH, BB), 256>>>(q, k, v);

    dim3 grid(LL / 128, HH, BB);
    attn10<<<grid, 128>>>(bw, out);
}

// round 14
// speedup vs baseline: 4.7665x; 1.0230x over previous
#include <cuda_runtime.h>
#include <cstdint>

#define BB 2
#define LL 2048
#define HH 16
#define EE 64
#define NKT 32

// fp16x2 frag-major packed operands (layouts unchanged from R12/R13).
__device__ uint4 g_Qh[BB * HH * 256 * 2 * 32];
__device__ uint4 g_Kh[BB * HH * 256 * 2 * 32];
__device__ uint4 g_Vh[BB * HH * NKT * 16 * 32];

#define LOG2E 1.4426950408889634f
#define SCL2  0.18033688011112042592f   // 0.125 * log2(e)

__device__ __forceinline__ uint32_t packh2(float lo, float hi) {
    uint32_t r;
    asm("cvt.rn.f16x2.f32 %0, %1, %2;" : "=r"(r) : "f"(hi), "f"(lo));
    return r;
}
__device__ __forceinline__ float ex2f(float x) {
    float o;
    asm("ex2.approx.f32 %0, %1;" : "=f"(o) : "f"(x));
    return o;
}
__device__ __forceinline__ void mma16(float c[4], uint32_t a0, uint32_t a1,
                                      uint32_t a2, uint32_t a3,
                                      uint32_t b0, uint32_t b1) {
    asm volatile(
        "mma.sync.aligned.m16n8k16.row.col.f32.f16.f16.f32 "
        "{%0,%1,%2,%3}, {%4,%5,%6,%7}, {%8,%9}, {%0,%1,%2,%3};"
        : "+f"(c[0]), "+f"(c[1]), "+f"(c[2]), "+f"(c[3])
        : "r"(a0), "r"(a1), "r"(a2), "r"(a3), "r"(b0), "r"(b1));
}

// ---------------------------------------------------------------------------
// Fused prepass (unchanged — proven).
// ---------------------------------------------------------------------------
__global__ void prep_kernel(const float* __restrict__ q,
                            const float* __restrict__ k,
                            const float* __restrict__ v) {
    __shared__ float sq[64 * 65];
    __shared__ float sk[64 * 65];
    const int kt = blockIdx.x, h = blockIdx.y, b = blockIdx.z;
    const int bh = b * HH + h;
    const int tid = threadIdx.x;

    #pragma unroll
    for (int it = 0; it < 4; it++) {
        int i = it * 256 + tid;
        int j = i >> 4, e4 = i & 15;
        int l = kt * 64 + j;
        size_t gidx = ((size_t)(b * LL + l) * HH + h) * 16 + e4;
        float4 vq = ((const float4*)q)[gidx];
        float4 vk = ((const float4*)k)[gidx];
        if (e4 < 8) {
            float i0 = (float)(e4 * 2);
            const float NEG_L2 = -0.83048202372184058696f;  // -log2(10000)/16
            float s0, c0, s1, c1;
            sincosf((float)l * exp2f(i0 * NEG_L2), &s0, &c0);
            sincosf((float)l * exp2f((i0 + 1.0f) * NEG_L2), &s1, &c1);
            float4 o;
            o.x = c0 * vq.x - s0 * vq.y;  o.y = c0 * vq.y + s0 * vq.x;
            o.z = c1 * vq.z - s1 * vq.w;  o.w = c1 * vq.w + s1 * vq.z;
            vq = o;
            o.x = c0 * vk.x - s0 * vk.y;  o.y = c0 * vk.y + s0 * vk.x;
            o.z = c1 * vk.z - s1 * vk.w;  o.w = c1 * vk.w + s1 * vk.z;
            vk = o;
        }
        int e = e4 * 4;
        sq[j * 65 + e + 0] = vq.x; sq[j * 65 + e + 1] = vq.y;
        sq[j * 65 + e + 2] = vq.z; sq[j * 65 + e + 3] = vq.w;
        sk[j * 65 + e + 0] = vk.x; sk[j * 65 + e + 1] = vk.y;
        sk[j * 65 + e + 2] = vk.z; sk[j * 65 + e + 3] = vk.w;
    }
    __syncthreads();

    uint4* Qh = g_Qh + ((size_t)bh * 256 + kt * 8) * 2 * 32;
    uint4* Kh = g_Kh + ((size_t)bh * 256 + kt * 8) * 2 * 32;
    #pragma unroll
    for (int it = 0; it < 2; it++) {
        int i = it * 256 + tid;
        int lane = i & 31, x = i >> 5;       // x = grp*2 + kbp2
        int grp = x >> 1, kbp2 = x & 1;
        int g = lane >> 2, t = lane & 3;
        const float* s = sq + (grp * 8 + g) * 65 + kbp2 * 32 + 2 * t;
        uint4 o;
        o.x = packh2(s[0],  s[1]);
        o.y = packh2(s[8],  s[9]);
        o.z = packh2(s[16], s[17]);
        o.w = packh2(s[24], s[25]);
        Qh[x * 32 + lane] = o;
        const float* s2 = sk + (grp * 8 + g) * 65 + kbp2 * 32 + 2 * t;
        o.x = packh2(s2[0],  s2[1]);
        o.y = packh2(s2[8],  s2[9]);
        o.z = packh2(s2[16], s2[17]);
        o.w = packh2(s2[24], s2[25]);
        Kh[x * 32 + lane] = o;
    }
    __syncthreads();

    const float* Vg = v + ((size_t)(b * LL + kt * 64) * HH + h) * EE;
    #pragma unroll
    for (int it = 0; it < 4; it++) {
        int i = it * 256 + tid;
        int j = i >> 4, e = (i & 15) * 4;
        float4 w = *(const float4*)(Vg + (size_t)j * (HH * EE) + e);
        sq[j * 65 + e + 0] = w.x; sq[j * 65 + e + 1] = w.y;
        sq[j * 65 + e + 2] = w.z; sq[j * 65 + e + 3] = w.w;
    }
    __syncthreads();

    uint4* Vh = g_Vh + ((size_t)bh * NKT + kt) * 16 * 32;
    #pragma unroll
    for (int it = 0; it < 2; it++) {
        int i = it * 256 + tid;
        int lane = i & 31, x = i >> 5;       // x = nbp*4 + db2
        int nbp = x >> 2, db2 = x & 3;
        int g = lane >> 2, t = lane & 3;
        const float* v0 = sq + (16 * nbp + 2 * t) * 65 + 16 * db2 + g;
        uint4 o;
        o.x = packh2(v0[0],        v0[65]);
        o.y = packh2(v0[8 * 65],   v0[9 * 65]);
        o.z = packh2(v0[8],        v0[65 + 8]);
        o.w = packh2(v0[8 * 65 + 8], v0[9 * 65 + 8]);
        Vh[x * 32 + lane] = o;
    }
}

// ---- QK for one nbp pair: 4-8 mma into c0/c1 ----
__device__ __forceinline__ void qk_block(
    const uint32_t (&qa)[4][4], const uint4* __restrict__ Kt,
    int nbp, bool a1, float (&c0)[4], float (&c1)[4])
{
    const int nb0 = 2 * nbp;
    {
        uint4 k0 = Kt[nb0 * 64], k1 = Kt[nb0 * 64 + 32];
        mma16(c0, qa[0][0], qa[0][1], qa[0][2], qa[0][3], k0.x, k0.y);
        mma16(c0, qa[1][0], qa[1][1], qa[1][2], qa[1][3], k0.z, k0.w);
        mma16(c0, qa[2][0], qa[2][1], qa[2][2], qa[2][3], k1.x, k1.y);
        mma16(c0, qa[3][0], qa[3][1], qa[3][2], qa[3][3], k1.z, k1.w);
    }
    if (a1) {
        uint4 k0 = Kt[(nb0 + 1) * 64], k1 = Kt[(nb0 + 1) * 64 + 32];
        mma16(c1, qa[0][0], qa[0][1], qa[0][2], qa[0][3], k0.x, k0.y);
        mma16(c1, qa[1][0], qa[1][1], qa[1][2], qa[1][3], k0.z, k0.w);
        mma16(c1, qa[2][0], qa[2][1], qa[2][2], qa[2][3], k1.x, k1.y);
        mma16(c1, qa[3][0], qa[3][1], qa[3][2], qa[3][3], k1.z, k1.w);
    }
}

// ---------------------------------------------------------------------------
// One tile at one kt, software-pipelined: QK(nbp+1) issues between
// softmax(nbp) and PV(nbp) so the next QK chain executes under PV issue.
// ---------------------------------------------------------------------------
template <int NBPN>
__device__ __forceinline__ void tile_kt_pipe(
    int dep, int n0, const uint32_t (&qa)[4][4],
    const uint4* __restrict__ Kt, const uint4* __restrict__ Vt,
    float biasA, float biasB, int t,
    float (&oacc)[8][4], float& lsA, float& lsB)
{
    float c0[4] = {0, 0, 0, 0}, c1[4] = {0, 0, 0, 0};
    qk_block(qa, Kt, 0, (1 <= dep), c0, c1);

    #pragma unroll
    for (int nbp = 0; nbp < NBPN; nbp++) {
        const int nb0 = 2 * nbp, nb1 = nb0 + 1;
        if (nb0 > dep) continue;              // tail-only skip
        const bool a1 = (nb1 <= dep);

        // ---- softmax(nbp); shuffle-free P frags ----
        uint32_t pa0, pa1, pa2, pa3;
        {
            const int ci = nb0 * 8 + 2 * t;
            float p0 = (ci     <= n0) ? ex2f(fmaf(c0[0], SCL2, biasA)) : 0.0f;
            float p1 = (ci + 1 <= n0) ? ex2f(fmaf(c0[1], SCL2, biasA)) : 0.0f;
            float p2 = (ci     <= n0) ? ex2f(fmaf(c0[2], SCL2, biasB)) : 0.0f;
            float p3 = (ci + 1 <= n0) ? ex2f(fmaf(c0[3], SCL2, biasB)) : 0.0f;
            lsA += p0 + p1;
            lsB += p2 + p3;
            pa0 = packh2(p0, p1);
            pa1 = packh2(p2, p3);
        }
        if (a1) {
            const int ci = nb1 * 8 + 2 * t;
            float p0 = (ci     <= n0) ? ex2f(fmaf(c1[0], SCL2, biasA)) : 0.0f;
            float p1 = (ci + 1 <= n0) ? ex2f(fmaf(c1[1], SCL2, biasA)) : 0.0f;
            float p2 = (ci     <= n0) ? ex2f(fmaf(c1[2], SCL2, biasB)) : 0.0f;
            float p3 = (ci + 1 <= n0) ? ex2f(fmaf(c1[3], SCL2, biasB)) : 0.0f;
            lsA += p0 + p1;
            lsB += p2 + p3;
            pa2 = packh2(p0, p1);
            pa3 = packh2(p2, p3);
        } else {
            pa2 = 0u; pa3 = 0u;
        }

        // ---- QK(nbp+1) issued ahead of PV(nbp) (independent chains) ----
        float d0[4] = {0, 0, 0, 0}, d1[4] = {0, 0, 0, 0};
        const bool nxt = (nbp + 1 < NBPN) && (2 * (nbp + 1) <= dep);
        if (nxt)
            qk_block(qa, Kt, nbp + 1, (2 * (nbp + 1) + 1 <= dep), d0, d1);

        // ---- PV(nbp) ----
        #pragma unroll
        for (int db2 = 0; db2 < 4; db2++) {
            uint4 vv = Vt[(nbp * 4 + db2) * 32];
            mma16(oacc[2 * db2],     pa0, pa1, pa2, pa3, vv.x, vv.y);
            mma16(oacc[2 * db2 + 1], pa0, pa1, pa2, pa3, vv.z, vv.w);
        }

        // rotate pipeline registers
        #pragma unroll
        for (int i = 0; i < 4; i++) { c0[i] = d0[i]; c1[i] = d1[i]; }
    }
}

// ---------------------------------------------------------------------------
// Main attention: balanced dual-tile warps (R13) + software pipelining.
// 128 threads = 4 warps; warp w owns depth tiles {w, 7-w} -> 9 blocks/kt.
// ---------------------------------------------------------------------------
__global__ __launch_bounds__(128, 4)
void attn11(const float* __restrict__ bw, float* __restrict__ out) {
    const int tid  = threadIdx.x;
    const int lane = tid & 31;
    const int w    = tid >> 5;       // 0..3
    const int g    = lane >> 2;
    const int t    = lane & 3;
    const int qtb  = blockIdx.x;
    const int h    = blockIdx.y;
    const int b    = blockIdx.z;
    const int bh   = b * HH + h;
    const int l0   = qtb * 128;

    const float b2s = bw[HH + h] * LOG2E;
    const float b2d = bw[h] * LOG2E;

    const int dep0 = w;              // light tile
    const int dep1 = 7 - w;          // heavy tile
    const int n00  = 8 * dep0 + g;
    const int n01  = 8 * dep1 + g;

    uint32_t qa0[4][4], qa1[4][4];
    {
        const uint4* QA = g_Qh + ((size_t)bh * 256 + qtb * 16 + dep0) * 64 + lane;
        const uint4* QB = QA + 8 * 64;
        uint4 a0 = QA[0], a1 = QA[32], b0 = QB[0], b1 = QB[32];
        qa0[0][0] = a0.x; qa0[0][1] = b0.x; qa0[0][2] = a0.y; qa0[0][3] = b0.y;
        qa0[1][0] = a0.z; qa0[1][1] = b0.z; qa0[1][2] = a0.w; qa0[1][3] = b0.w;
        qa0[2][0] = a1.x; qa0[2][1] = b1.x; qa0[2][2] = a1.y; qa0[2][3] = b1.y;
        qa0[3][0] = a1.z; qa0[3][1] = b1.z; qa0[3][2] = a1.w; qa0[3][3] = b1.w;
    }
    {
        const uint4* QA = g_Qh + ((size_t)bh * 256 + qtb * 16 + dep1) * 64 + lane;
        const uint4* QB = QA + 8 * 64;
        uint4 a0 = QA[0], a1 = QA[32], b0 = QB[0], b1 = QB[32];
        qa1[0][0] = a0.x; qa1[0][1] = b0.x; qa1[0][2] = a0.y; qa1[0][3] = b0.y;
        qa1[1][0] = a0.z; qa1[1][1] = b0.z; qa1[1][2] = a0.w; qa1[1][3] = b0.w;
        qa1[2][0] = a1.x; qa1[2][1] = b1.x; qa1[2][2] = a1.y; qa1[2][3] = b1.y;
        qa1[3][0] = a1.z; qa1[3][1] = b1.z; qa1[3][2] = a1.w; qa1[3][3] = b1.w;
    }

    float o0[8][4], o1[8][4];
    #pragma unroll
    for (int db = 0; db < 8; db++)
        #pragma unroll
        for (int i = 0; i < 4; i++) { o0[db][i] = 0.0f; o1[db][i] = 0.0f; }
    float lsA0 = 0.0f, lsB0 = 0.0f, lsA1 = 0.0f, lsB1 = 0.0f;

    const uint4* Kf0 = g_Kh + (size_t)bh * 256 * 64 + lane;
    const uint4* Vf0 = g_Vh + (size_t)bh * NKT * 512 + lane;

    for (int kt = 0; kt < NKT; kt++) {
        const uint4* Kt = Kf0 + (size_t)kt * 8 * 64;
        const uint4* Vt = Vf0 + (size_t)kt * 512;
        const float biasA = (kt == 2 * qtb)     ? b2s : b2d;
        const float biasB = (kt == 2 * qtb + 1) ? b2s : b2d;

        tile_kt_pipe<2>(dep0, n00, qa0, Kt, Vt, biasA, biasB, t, o0, lsA0, lsB0);
        tile_kt_pipe<4>(dep1, n01, qa1, Kt, Vt, biasA, biasB, t, o1, lsA1, lsB1);
    }

    #pragma unroll
    for (int ti = 0; ti < 2; ti++) {
        float lsA = ti ? lsA1 : lsA0;
        float lsB = ti ? lsB1 : lsB0;
        lsA += __shfl_xor_sync(0xffffffffu, lsA, 1);
        lsA += __shfl_xor_sync(0xffffffffu, lsA, 2);
        lsB += __shfl_xor_sync(0xffffffffu, lsB, 1);
        lsB += __shfl_xor_sync(0xffffffffu, lsB, 2);
        const float invA = 1.0f / lsA;
        const float invB = 1.0f / lsB;
        float (*oacc)[4] = ti ? o1 : o0;
        const int dep = ti ? dep1 : dep0;
        const int rowA = l0 + 8 * dep + g;
        const int rowB = rowA + 64;
        #pragma unroll
        for (int db = 0; db < 8; db++) {
            float2 v0;
            v0.x = oacc[db][0] * invA;
            v0.y = oacc[db][1] * invA;
            *(float2*)(out + (((size_t)(b * LL + rowA)) * HH + h) * EE + db * 8 + 2 * t) = v0;
            float2 v1;
            v1.x = oacc[db][2] * invB;
            v1.y = oacc[db][3] * invB;
            *(float2*)(out + (((size_t)(b * LL + rowB)) * HH + h) * EE + db * 8 + 2 * t) = v1;
        }
    }
}

// ---------------------------------------------------------------------------
extern "C" void kernel_launch(void* const* d_in, const int* in_sizes, int n_in,
                              void* d_out, int out_size) {
    const float* q  = (const float*)d_in[0];
    const float* k  = (const float*)d_in[1];
    const float* v  = (const float*)d_in[2];
    const float* bw = (const float*)d_in[3];
    float* out = (float*)d_out;

    prep_kernel<<<dim3(NKT, HH, BB), 256>>>(q, k, v);

    dim3 grid(LL / 128, HH, BB);
    attn11<<<grid, 128>>>(bw, out);
}